// round 12
// baseline (speedup 1.0000x reference)
#include <cuda_runtime.h>
#include <cuda_bf16.h>
#include <cstdint>

#define BATCH 2048
#define NCLS  1000
#define FDIM  128

#define BM 128
#define BN 64
#define GRID_CTAS 256
#define RSTRIDE 272          // 256B (128 bf16) + 16B pad

#define SM_A 0
#define SM_B (128 * RSTRIDE)             // 34816
#define SM_LAB (SM_B + 64 * RSTRIDE)     // 52224
#define SM_FN  (SM_LAB + 512)            // 52736
#define SM_CN  (SM_FN + 512)             // 53248
#define SMEM_BYTES (SM_CN + 256)         // 53504
#define WBSTRIDE 36                      // f32 words per wbuf row
#define WBSZ (32 * WBSTRIDE * 4)         // 4608B per warp (aliases A/B region)

__device__ float g_fn[BATCH];
__device__ float g_cn[1024];             // rows 1000..1023 stay static-zero
__device__ __nv_bfloat16 g_featb[BATCH * FDIM];
__device__ __nv_bfloat16 g_cenb[1024 * FDIM];   // pad rows stay static-zero
__device__ unsigned g_arrive;            // soft-barrier counters (self-reset)
__device__ unsigned g_done;

__device__ __forceinline__ uint32_t smem_to_u32(const void* p) {
    uint32_t a;
    asm("{ .reg .u64 t; cvta.to.shared.u64 t, %1; cvt.u32.u64 %0, t; }" : "=r"(a) : "l"(p));
    return a;
}
__device__ __forceinline__ void ldm_x4(uint32_t* r, uint32_t addr) {
    asm volatile("ldmatrix.sync.aligned.m8n8.x4.shared.b16 {%0,%1,%2,%3}, [%4];"
                 : "=r"(r[0]), "=r"(r[1]), "=r"(r[2]), "=r"(r[3]) : "r"(addr));
}
__device__ __forceinline__ void mma_bf16(float* c, const uint32_t* a, const uint32_t* b) {
    asm volatile("mma.sync.aligned.m16n8k16.row.col.f32.bf16.bf16.f32 "
                 "{%0,%1,%2,%3}, {%4,%5,%6,%7}, {%8,%9}, {%0,%1,%2,%3};"
                 : "+f"(c[0]), "+f"(c[1]), "+f"(c[2]), "+f"(c[3])
                 : "r"(a[0]), "r"(a[1]), "r"(a[2]), "r"(a[3]), "r"(b[0]), "r"(b[1]));
}
__device__ __forceinline__ void cp16(uint32_t dst, const void* src) {
    asm volatile("cp.async.cg.shared.global [%0], [%1], 16;" :: "r"(dst), "l"(src));
}
__device__ __forceinline__ uint32_t bf2(float lo, float hi) {
    uint32_t r;
    asm("cvt.rn.bf16x2.f32 %0, %1, %2;" : "=r"(r) : "f"(hi), "f"(lo));
    return r;
}

// ---------------------------------------------------------------------------
// ONE kernel. Phase 0: each CTA converts its 1/256 slice of feat+centers to
// bf16 globals + fp32 norms. Device-wide soft barrier (all 256 CTAs are
// co-resident at oe=2). Phase 1: R4's GEMM + epilogue.
// ---------------------------------------------------------------------------
__global__ __launch_bounds__(256, 2) void lgm_fused(const float* __restrict__ feat,
                                                    const int*   __restrict__ labelw,
                                                    const float* __restrict__ centers,
                                                    float* __restrict__ out) {
    extern __shared__ __align__(16) unsigned char smem[];
    const uint32_t sb = smem_to_u32(smem);
    int*   lab_s = (int*)(smem + SM_LAB);
    float* fn_s  = (float*)(smem + SM_FN);
    float* cn_s  = (float*)(smem + SM_CN);

    const int t    = threadIdx.x;
    const int wid  = t >> 5;
    const int lane = t & 31;
    const int bm   = blockIdx.y * BM;
    const int bn   = blockIdx.x * BN;
    const int cta  = blockIdx.y * 16 + blockIdx.x;
    const int wm   = wid & 3;    // 0..3 : 32-row slab
    const int wn   = wid >> 2;   // 0..1 : 32-col slab

    // label dtype sample (odd int32 words all-zero => int64)
    const int nz = (labelw[8 * t + 1] != 0);

    // ---- Phase 0: convert this CTA's slice (8 feat rows, 4 center rows) ----
    {
        int r = cta * 8 + wid;                           // 0..2047, one row/warp
        float4 v = ((const float4*)(feat + (size_t)r * FDIM))[lane];
        float s = v.x * v.x + v.y * v.y + v.z * v.z + v.w * v.w;
        #pragma unroll
        for (int o = 16; o > 0; o >>= 1) s += __shfl_xor_sync(0xffffffffu, s, o);
        if (lane == 0) g_fn[r] = s;
        *(uint2*)(g_featb + (size_t)r * FDIM + lane * 4) =
            make_uint2(bf2(v.x, v.y), bf2(v.z, v.w));

        if (wid < 4) {
            int c = cta * 4 + wid;                       // 0..1023
            if (c < NCLS) {
                float4 w = ((const float4*)(centers + (size_t)c * FDIM))[lane];
                float sc = w.x * w.x + w.y * w.y + w.z * w.z + w.w * w.w;
                #pragma unroll
                for (int o = 16; o > 0; o >>= 1) sc += __shfl_xor_sync(0xffffffffu, sc, o);
                if (lane == 0) g_cn[c] = sc;
                *(uint2*)(g_cenb + (size_t)c * FDIM + lane * 4) =
                    make_uint2(bf2(w.x, w.y), bf2(w.z, w.w));
            }
        }
        if (cta == 0 && t == 0) out[2 * (size_t)BATCH * NCLS] = 0.0f;
    }

    __threadfence();   // publish phase-0 writes (all threads)
    const int shift = (__syncthreads_or(nz) == 0) ? 1 : 0;   // 1 => int64 labels

    // ---- device-wide soft barrier ----
    if (t == 0) {
        atomicAdd(&g_arrive, 1u);
        while (*(volatile unsigned*)&g_arrive < GRID_CTAS) __nanosleep(64);
        __threadfence();   // acquire
    }
    __syncthreads();

    // ---- Phase 1: stage tiles via cp.async (R4 geometry) ----
    #pragma unroll
    for (int i = 0; i < 8; i++) {
        int idx = t + (i << 8);
        int row = idx >> 4, seg = idx & 15;
        cp16(sb + SM_A + row * RSTRIDE + seg * 16,
             (const unsigned char*)g_featb + (size_t)(bm + row) * 256 + seg * 16);
    }
    #pragma unroll
    for (int i = 0; i < 4; i++) {
        int idx = t + (i << 8);
        int row = idx >> 4, seg = idx & 15;
        cp16(sb + SM_B + row * RSTRIDE + seg * 16,
             (const unsigned char*)g_cenb + (size_t)(bn + row) * 256 + seg * 16);
    }
    if (t < 32)       cp16(sb + SM_FN + t * 16, (const unsigned char*)(g_fn + bm) + t * 16);
    else if (t < 48)  cp16(sb + SM_CN + (t - 32) * 16, (const unsigned char*)(g_cn + bn) + (t - 32) * 16);
    asm volatile("cp.async.commit_group;" ::: "memory");

    if (t < BM) lab_s[t] = labelw[(bm + t) << shift];

    float acc[2][4][4];
    #pragma unroll
    for (int mi = 0; mi < 2; mi++)
        #pragma unroll
        for (int ni = 0; ni < 4; ni++)
            #pragma unroll
            for (int r = 0; r < 4; r++) acc[mi][ni][r] = 0.0f;

    const uint32_t aBase = sb + SM_A + (uint32_t)(wm * 32 + (lane & 15)) * RSTRIDE + (lane >> 4) * 16;
    const uint32_t bBase = sb + SM_B + (uint32_t)(wn * 32 + (lane & 7) + (lane >> 4) * 8) * RSTRIDE
                              + ((lane >> 3) & 1) * 16;

    asm volatile("cp.async.wait_group 0;" ::: "memory");
    __syncthreads();

    #pragma unroll
    for (int ks = 0; ks < 8; ks++) {
        uint32_t a[2][4], b[2][4];
        #pragma unroll
        for (int mi = 0; mi < 2; mi++)
            ldm_x4(a[mi], aBase + (uint32_t)(mi * 16) * RSTRIDE + ks * 32);
        #pragma unroll
        for (int nj = 0; nj < 2; nj++)
            ldm_x4(b[nj], bBase + (uint32_t)(nj * 16) * RSTRIDE + ks * 32);
        #pragma unroll
        for (int mi = 0; mi < 2; mi++)
            #pragma unroll
            for (int ni = 0; ni < 4; ni++)
                mma_bf16(acc[mi][ni], a[mi], &b[ni >> 1][(ni & 1) * 2]);
    }

    // ---- epilogue pass 1: logits -> per-warp smem buffer (aliases A/B) ----
    __syncthreads();   // all warps done reading A/B smem
    float* wbuf = (float*)(smem + wid * WBSZ);   // [32][WBSTRIDE]
    const int r4 = lane >> 2;
    const int c2 = (lane & 3) * 2;

    float cnv[4][2];
    #pragma unroll
    for (int ni = 0; ni < 4; ni++) {
        int cl = wn * 32 + ni * 8 + c2;
        cnv[ni][0] = cn_s[cl];
        cnv[ni][1] = cn_s[cl + 1];
    }

    float lik = 0.0f;
    #pragma unroll
    for (int mi = 0; mi < 2; mi++) {
        #pragma unroll
        for (int rh = 0; rh < 2; rh++) {
            int rr   = mi * 16 + rh * 8 + r4;
            int rloc = wm * 32 + rr;
            float fn = fn_s[rloc];
            int   lb = lab_s[rloc];
            #pragma unroll
            for (int ni = 0; ni < 4; ni++) {
                int c0 = bn + wn * 32 + ni * 8 + c2;
                float dist0 = fn + cnv[ni][0] - 2.0f * acc[mi][ni][rh * 2 + 0];
                float dist1 = fn + cnv[ni][1] - 2.0f * acc[mi][ni][rh * 2 + 1];
                if (c0 == lb)     lik += dist0;
                if (c0 + 1 == lb) lik += dist1;
                *(float2*)(wbuf + rr * WBSTRIDE + ni * 8 + c2) =
                    make_float2(-0.5f * dist0, -0.5f * dist1);
            }
        }
    }
    __syncwarp();

    // ---- epilogue pass 2: coalesced STG.128 ----
    float* __restrict__ mout = out + (size_t)BATCH * NCLS;
    const int lrow = lane >> 3;
    const int lcol = (lane & 7) * 4;
    const int cg   = bn + wn * 32 + lcol;
    if (cg < NCLS) {
        #pragma unroll
        for (int it = 0; it < 8; it++) {
            int rr = it * 4 + lrow;
            float4 lv = *(float4*)(wbuf + rr * WBSTRIDE + lcol);
            int rloc = wm * 32 + rr;
            int lb   = lab_s[rloc];
            size_t o = (size_t)(bm + rloc) * NCLS + cg;
            *(float4*)(out + o) = lv;
            float4 mv = lv;
            if (cg     == lb) mv.x *= 2.0f;
            if (cg + 1 == lb) mv.y *= 2.0f;
            if (cg + 2 == lb) mv.z *= 2.0f;
            if (cg + 3 == lb) mv.w *= 2.0f;
            *(float4*)(mout + o) = mv;
        }
    }

    #pragma unroll
    for (int o = 16; o > 0; o >>= 1) lik += __shfl_xor_sync(0xffffffffu, lik, o);
    if (lane == 0 && lik != 0.0f)
        atomicAdd(out + 2 * (size_t)BATCH * NCLS, lik * (1.0f / (2.0f * (float)BATCH)));

    // ---- counter self-reset (deterministic across graph replays) ----
    if (t == 0) {
        unsigned d = atomicAdd(&g_done, 1u);
        if (d == GRID_CTAS - 1) {   // every CTA has passed the barrier & finished
            *(volatile unsigned*)&g_arrive = 0u;
            *(volatile unsigned*)&g_done   = 0u;
            __threadfence();
        }
    }
}

extern "C" void kernel_launch(void* const* d_in, const int* in_sizes, int n_in,
                              void* d_out, int out_size) {
    const float* feat    = (const float*)d_in[0];
    const int*   labelw  = (const int*)d_in[1];
    const float* centers = (const float*)d_in[2];
    float* out = (float*)d_out;

    cudaFuncSetAttribute(lgm_fused, cudaFuncAttributeMaxDynamicSharedMemorySize, SMEM_BYTES);

    dim3 grid(1024 / BN, BATCH / BM);   // 16 x 16 = 256 CTAs
    lgm_fused<<<grid, 256, SMEM_BYTES>>>(feat, labelw, centers, out);
}

// round 13
// speedup vs baseline: 1.1830x; 1.1830x over previous
#include <cuda_runtime.h>
#include <cuda_bf16.h>
#include <cstdint>

#define BATCH 2048
#define NCLS  1000
#define FDIM  128

#define BM 128
#define BN 64
#define GRID_CTAS 256
#define RSTRIDE 272          // 256B (128 bf16) + 16B pad

#define SM_A 0
#define SM_B (128 * RSTRIDE)             // 34816
#define SM_LAB (SM_B + 64 * RSTRIDE)     // 52224
#define SM_FN  (SM_LAB + 512)            // 52736
#define SM_CN  (SM_FN + 512)             // 53248
#define SMEM_BYTES (SM_CN + 256)         // 53504
#define WBSTRIDE 36                      // f32 words per wbuf row
#define WBSZ (32 * WBSTRIDE * 4)         // 4608B per warp (aliases A/B region)

__device__ float g_fn[BATCH];
__device__ float g_cn[1024];             // rows 1000..1023 stay static-zero
__device__ __nv_bfloat16 g_featb[BATCH * FDIM];
__device__ __nv_bfloat16 g_cenb[1024 * FDIM];   // pad rows stay static-zero
__device__ unsigned g_arrive;            // soft-barrier counters (self-reset)
__device__ unsigned g_done;

__device__ __forceinline__ uint32_t smem_to_u32(const void* p) {
    uint32_t a;
    asm("{ .reg .u64 t; cvta.to.shared.u64 t, %1; cvt.u32.u64 %0, t; }" : "=r"(a) : "l"(p));
    return a;
}
__device__ __forceinline__ void ldm_x4(uint32_t* r, uint32_t addr) {
    asm volatile("ldmatrix.sync.aligned.m8n8.x4.shared.b16 {%0,%1,%2,%3}, [%4];"
                 : "=r"(r[0]), "=r"(r[1]), "=r"(r[2]), "=r"(r[3]) : "r"(addr));
}
__device__ __forceinline__ void mma_bf16(float* c, const uint32_t* a, const uint32_t* b) {
    asm volatile("mma.sync.aligned.m16n8k16.row.col.f32.bf16.bf16.f32 "
                 "{%0,%1,%2,%3}, {%4,%5,%6,%7}, {%8,%9}, {%0,%1,%2,%3};"
                 : "+f"(c[0]), "+f"(c[1]), "+f"(c[2]), "+f"(c[3])
                 : "r"(a[0]), "r"(a[1]), "r"(a[2]), "r"(a[3]), "r"(b[0]), "r"(b[1]));
}
__device__ __forceinline__ void cp16(uint32_t dst, const void* src) {
    asm volatile("cp.async.cg.shared.global [%0], [%1], 16;" :: "r"(dst), "l"(src));
}
__device__ __forceinline__ uint32_t bf2(float lo, float hi) {
    uint32_t r;
    asm("cvt.rn.bf16x2.f32 %0, %1, %2;" : "=r"(r) : "f"(hi), "f"(lo));
    return r;
}

// ---------------------------------------------------------------------------
// ONE kernel. Phase 0: each CTA converts its 1/256 slice of feat+centers to
// bf16 globals + fp32 norms. Device-wide soft barrier (all 256 CTAs are
// co-resident at oe=2). Phase 1: R4's GEMM + epilogue.
// ---------------------------------------------------------------------------
__global__ __launch_bounds__(256, 2) void lgm_fused(const float* __restrict__ feat,
                                                    const int*   __restrict__ labelw,
                                                    const float* __restrict__ centers,
                                                    float* __restrict__ out) {
    extern __shared__ __align__(16) unsigned char smem[];
    const uint32_t sb = smem_to_u32(smem);
    int*   lab_s = (int*)(smem + SM_LAB);
    float* fn_s  = (float*)(smem + SM_FN);
    float* cn_s  = (float*)(smem + SM_CN);

    const int t    = threadIdx.x;
    const int wid  = t >> 5;
    const int lane = t & 31;
    const int bm   = blockIdx.y * BM;
    const int bn   = blockIdx.x * BN;
    const int cta  = blockIdx.y * 16 + blockIdx.x;
    const int wm   = wid & 3;    // 0..3 : 32-row slab
    const int wn   = wid >> 2;   // 0..1 : 32-col slab

    // label dtype sample (odd int32 words all-zero => int64)
    const int nz = (labelw[8 * t + 1] != 0);

    // ---- Phase 0: convert this CTA's slice (8 feat rows, 4 center rows) ----
    {
        int r = cta * 8 + wid;                           // 0..2047, one row/warp
        float4 v = ((const float4*)(feat + (size_t)r * FDIM))[lane];
        float s = v.x * v.x + v.y * v.y + v.z * v.z + v.w * v.w;
        #pragma unroll
        for (int o = 16; o > 0; o >>= 1) s += __shfl_xor_sync(0xffffffffu, s, o);
        if (lane == 0) g_fn[r] = s;
        *(uint2*)(g_featb + (size_t)r * FDIM + lane * 4) =
            make_uint2(bf2(v.x, v.y), bf2(v.z, v.w));

        if (wid < 4) {
            int c = cta * 4 + wid;                       // 0..1023
            if (c < NCLS) {
                float4 w = ((const float4*)(centers + (size_t)c * FDIM))[lane];
                float sc = w.x * w.x + w.y * w.y + w.z * w.z + w.w * w.w;
                #pragma unroll
                for (int o = 16; o > 0; o >>= 1) sc += __shfl_xor_sync(0xffffffffu, sc, o);
                if (lane == 0) g_cn[c] = sc;
                *(uint2*)(g_cenb + (size_t)c * FDIM + lane * 4) =
                    make_uint2(bf2(w.x, w.y), bf2(w.z, w.w));
            }
        }
        if (cta == 0 && t == 0) out[2 * (size_t)BATCH * NCLS] = 0.0f;
    }

    __threadfence();   // publish phase-0 writes (all threads)
    const int shift = (__syncthreads_or(nz) == 0) ? 1 : 0;   // 1 => int64 labels

    // ---- device-wide soft barrier ----
    if (t == 0) {
        atomicAdd(&g_arrive, 1u);
        while (*(volatile unsigned*)&g_arrive < GRID_CTAS) __nanosleep(64);
        __threadfence();   // acquire
    }
    __syncthreads();

    // ---- Phase 1: stage tiles via cp.async (R4 geometry) ----
    #pragma unroll
    for (int i = 0; i < 8; i++) {
        int idx = t + (i << 8);
        int row = idx >> 4, seg = idx & 15;
        cp16(sb + SM_A + row * RSTRIDE + seg * 16,
             (const unsigned char*)g_featb + (size_t)(bm + row) * 256 + seg * 16);
    }
    #pragma unroll
    for (int i = 0; i < 4; i++) {
        int idx = t + (i << 8);
        int row = idx >> 4, seg = idx & 15;
        cp16(sb + SM_B + row * RSTRIDE + seg * 16,
             (const unsigned char*)g_cenb + (size_t)(bn + row) * 256 + seg * 16);
    }
    if (t < 32)       cp16(sb + SM_FN + t * 16, (const unsigned char*)(g_fn + bm) + t * 16);
    else if (t < 48)  cp16(sb + SM_CN + (t - 32) * 16, (const unsigned char*)(g_cn + bn) + (t - 32) * 16);
    asm volatile("cp.async.commit_group;" ::: "memory");

    if (t < BM) lab_s[t] = labelw[(bm + t) << shift];

    float acc[2][4][4];
    #pragma unroll
    for (int mi = 0; mi < 2; mi++)
        #pragma unroll
        for (int ni = 0; ni < 4; ni++)
            #pragma unroll
            for (int r = 0; r < 4; r++) acc[mi][ni][r] = 0.0f;

    const uint32_t aBase = sb + SM_A + (uint32_t)(wm * 32 + (lane & 15)) * RSTRIDE + (lane >> 4) * 16;
    const uint32_t bBase = sb + SM_B + (uint32_t)(wn * 32 + (lane & 7) + (lane >> 4) * 8) * RSTRIDE
                              + ((lane >> 3) & 1) * 16;

    asm volatile("cp.async.wait_group 0;" ::: "memory");
    __syncthreads();

    #pragma unroll
    for (int ks = 0; ks < 8; ks++) {
        uint32_t a[2][4], b[2][4];
        #pragma unroll
        for (int mi = 0; mi < 2; mi++)
            ldm_x4(a[mi], aBase + (uint32_t)(mi * 16) * RSTRIDE + ks * 32);
        #pragma unroll
        for (int nj = 0; nj < 2; nj++)
            ldm_x4(b[nj], bBase + (uint32_t)(nj * 16) * RSTRIDE + ks * 32);
        #pragma unroll
        for (int mi = 0; mi < 2; mi++)
            #pragma unroll
            for (int ni = 0; ni < 4; ni++)
                mma_bf16(acc[mi][ni], a[mi], &b[ni >> 1][(ni & 1) * 2]);
    }

    // ---- epilogue pass 1: logits -> per-warp smem buffer (aliases A/B) ----
    __syncthreads();   // all warps done reading A/B smem
    float* wbuf = (float*)(smem + wid * WBSZ);   // [32][WBSTRIDE]
    const int r4 = lane >> 2;
    const int c2 = (lane & 3) * 2;

    float cnv[4][2];
    #pragma unroll
    for (int ni = 0; ni < 4; ni++) {
        int cl = wn * 32 + ni * 8 + c2;
        cnv[ni][0] = cn_s[cl];
        cnv[ni][1] = cn_s[cl + 1];
    }

    float lik = 0.0f;
    #pragma unroll
    for (int mi = 0; mi < 2; mi++) {
        #pragma unroll
        for (int rh = 0; rh < 2; rh++) {
            int rr   = mi * 16 + rh * 8 + r4;
            int rloc = wm * 32 + rr;
            float fn = fn_s[rloc];
            int   lb = lab_s[rloc];
            #pragma unroll
            for (int ni = 0; ni < 4; ni++) {
                int c0 = bn + wn * 32 + ni * 8 + c2;
                float dist0 = fn + cnv[ni][0] - 2.0f * acc[mi][ni][rh * 2 + 0];
                float dist1 = fn + cnv[ni][1] - 2.0f * acc[mi][ni][rh * 2 + 1];
                if (c0 == lb)     lik += dist0;
                if (c0 + 1 == lb) lik += dist1;
                *(float2*)(wbuf + rr * WBSTRIDE + ni * 8 + c2) =
                    make_float2(-0.5f * dist0, -0.5f * dist1);
            }
        }
    }
    __syncwarp();

    // ---- epilogue pass 2: coalesced STG.128 ----
    float* __restrict__ mout = out + (size_t)BATCH * NCLS;
    const int lrow = lane >> 3;
    const int lcol = (lane & 7) * 4;
    const int cg   = bn + wn * 32 + lcol;
    if (cg < NCLS) {
        #pragma unroll
        for (int it = 0; it < 8; it++) {
            int rr = it * 4 + lrow;
            float4 lv = *(float4*)(wbuf + rr * WBSTRIDE + lcol);
            int rloc = wm * 32 + rr;
            int lb   = lab_s[rloc];
            size_t o = (size_t)(bm + rloc) * NCLS + cg;
            *(float4*)(out + o) = lv;
            float4 mv = lv;
            if (cg     == lb) mv.x *= 2.0f;
            if (cg + 1 == lb) mv.y *= 2.0f;
            if (cg + 2 == lb) mv.z *= 2.0f;
            if (cg + 3 == lb) mv.w *= 2.0f;
            *(float4*)(mout + o) = mv;
        }
    }

    #pragma unroll
    for (int o = 16; o > 0; o >>= 1) lik += __shfl_xor_sync(0xffffffffu, lik, o);
    if (lane == 0 && lik != 0.0f)
        atomicAdd(out + 2 * (size_t)BATCH * NCLS, lik * (1.0f / (2.0f * (float)BATCH)));

    // ---- counter self-reset (deterministic across graph replays) ----
    if (t == 0) {
        unsigned d = atomicAdd(&g_done, 1u);
        if (d == GRID_CTAS - 1) {   // every CTA has passed the barrier & finished
            *(volatile unsigned*)&g_arrive = 0u;
            *(volatile unsigned*)&g_done   = 0u;
            __threadfence();
        }
    }
}

extern "C" void kernel_launch(void* const* d_in, const int* in_sizes, int n_in,
                              void* d_out, int out_size) {
    const float* feat    = (const float*)d_in[0];
    const int*   labelw  = (const int*)d_in[1];
    const float* centers = (const float*)d_in[2];
    float* out = (float*)d_out;

    cudaFuncSetAttribute(lgm_fused, cudaFuncAttributeMaxDynamicSharedMemorySize, SMEM_BYTES);

    dim3 grid(1024 / BN, BATCH / BM);   // 16 x 16 = 256 CTAs
    lgm_fused<<<grid, 256, SMEM_BYTES>>>(feat, labelw, centers, out);
}